// round 16
// baseline (speedup 1.0000x reference)
#include <cuda_runtime.h>

// Staggered parallel transport, 8 paths, 32^4 lattice — fused single kernel.
// y-tile of 16 (512 threads): split producer/consumer barrier with legal
// arrival count (2*512 = 1024, the HW max; 2048 at 1024 threads trapped).
// Halo overhead halved vs the 8-row tile.
//
// Layouts (row-major, metadata order):
//   d_in[0] x_re : (8, V, 3) float    d_in[1] x_im : (8, V, 3)
//   d_in[2] U_re : (4, V, 9) float    d_in[3] U_im : (4, V, 9)
//   d_out        : (2, 8, V, 3) float   (re block then im block)
// site s = ((x*32 + y)*32 + z)*32 + t
//
// Channels:
//   0: copy            1: fwd mu=0       2: fwd mu=1   3: fwd mu=2
//   4: fwd mu=3        5: bwd mu=0 (scatter)   6: bwd mu=1 (scatter)
//   7: fwd mu=0 then fwd mu=1  — first hop in SMEM (y-tiled block + halo)
//
// Block = 512 threads = (t:32, y:16) at fixed (x, z).

#define VOL (32 * 32 * 32 * 32)

__device__ __forceinline__ void mv(const float* __restrict__ Ur,
                                   const float* __restrict__ Ui,
                                   const float* vr, const float* vi,
                                   float sgn, float* yr, float* yi) {
#pragma unroll
    for (int a = 0; a < 3; a++) {
        float sr = 0.f, si = 0.f;
#pragma unroll
        for (int b = 0; b < 3; b++) {
            float ur = Ur[a * 3 + b], ui = Ui[a * 3 + b];
            sr = fmaf(ur, vr[b], sr);
            sr = fmaf(-ui, vi[b], sr);
            si = fmaf(ur, vi[b], si);
            si = fmaf(ui, vr[b], si);
        }
        yr[a] = sgn * sr;
        yi[a] = sgn * si;
    }
}

__device__ __forceinline__ void mvdag(const float* __restrict__ Ur,
                                      const float* __restrict__ Ui,
                                      const float* vr, const float* vi,
                                      float sgn, float* yr, float* yi) {
#pragma unroll
    for (int a = 0; a < 3; a++) {
        float sr = 0.f, si = 0.f;
#pragma unroll
        for (int b = 0; b < 3; b++) {
            float ur = Ur[b * 3 + a], ui = Ui[b * 3 + a];  // conj-transpose
            sr = fmaf(ur, vr[b], sr);
            sr = fmaf(ui, vi[b], sr);
            si = fmaf(ur, vi[b], si);
            si = fmaf(-ui, vr[b], si);
        }
        yr[a] = sgn * sr;
        yi[a] = sgn * si;
    }
}

__device__ __forceinline__ void ldv(const float* __restrict__ xr,
                                    const float* __restrict__ xi,
                                    int ch, int s, float* vr, float* vi) {
    int b = (ch * VOL + s) * 3;
#pragma unroll
    for (int c = 0; c < 3; c++) {
        vr[c] = __ldg(xr + b + c);
        vi[c] = __ldg(xi + b + c);
    }
}

__device__ __forceinline__ void ldU(const float* __restrict__ Ur,
                                    const float* __restrict__ Ui,
                                    int mu, int s, float* ur, float* ui) {
    int b = (mu * VOL + s) * 9;
#pragma unroll
    for (int k = 0; k < 9; k++) {
        ur[k] = __ldg(Ur + b + k);
        ui[k] = __ldg(Ui + b + k);
    }
}

__device__ __forceinline__ void stv(float* __restrict__ out, int ch, int s,
                                    const float* yr, const float* yi) {
    int br = (ch * VOL + s) * 3;
    int bi = ((8 + ch) * VOL + s) * 3;
#pragma unroll
    for (int c = 0; c < 3; c++) {
        out[br + c] = yr[c];
        out[bi + c] = yi[c];
    }
}

__global__ void __launch_bounds__(512, 2)
k_fused(const float* __restrict__ xr, const float* __restrict__ xi,
        const float* __restrict__ Ur, const float* __restrict__ Ui,
        float* __restrict__ out) {
    // ch7 intermediate: [component 0..5][y-row 0..16][t]
    __shared__ float tmp_s[6][17][32];

    int tid = threadIdx.x;
    int t = tid & 31;
    int yl = tid >> 5;            // 0..15

    int bid = blockIdx.x;         // 0..2047
    int y0 = (bid & 1) << 4;      // {0, 16}
    int z = (bid >> 1) & 31;
    int x = bid >> 6;

    int y = y0 + yl;
    int s = (x << 15) | (y << 10) | (z << 5) | t;

    int s_px = (s & ~(31 << 15)) | (((x + 1) & 31) << 15);
    int s_py = (s & ~(31 << 10)) | (((y + 1) & 31) << 10);
    int s_pz = (s & ~(31 << 5)) | (((z + 1) & 31) << 5);
    int s_pt = (s & ~31) | ((t + 1) & 31);

    float eta1 = (x & 1) ? -1.f : 1.f;            // (-1)^x
    float eta2 = ((x ^ y) & 1) ? -1.f : 1.f;      // (-1)^(x+y)
    float eta3 = ((x ^ y ^ z) & 1) ? -1.f : 1.f;  // (-1)^(x+y+z)

    float vr[3], vi[3], yr[3], yi[3];

    // ch0: identity copy (short live range, early MLP)
    ldv(xr, xi, 0, s, vr, vi);
    stv(out, 0, s, vr, vi);

    // ---- mu = 0 block: U0(s) serves ch1, ch5, and the ch7 first hop ----
    {
        float U0r[9], U0i[9];
        ldU(Ur, Ui, 0, s, U0r, U0i);

        // ch1: out1(s) = U0(s) x1(s + x_hat)       (eta0 = 1)
        ldv(xr, xi, 1, s_px, vr, vi);
        mv(U0r, U0i, vr, vi, 1.f, yr, yi);
        stv(out, 1, s, yr, yi);

        // ch5 (scatter): out5(s + x_hat) = U0^dag(s) x5(s)
        ldv(xr, xi, 5, s, vr, vi);
        mvdag(U0r, U0i, vr, vi, 1.f, yr, yi);
        stv(out, 5, s_px, yr, yi);

        // ch7 first hop -> smem: tmp(s) = U0(s) x7(s + x_hat)
        ldv(xr, xi, 7, s_px, vr, vi);
        mv(U0r, U0i, vr, vi, 1.f, yr, yi);
#pragma unroll
        for (int c = 0; c < 3; c++) {
            tmp_s[c][yl][t] = yr[c];
            tmp_s[3 + c][yl][t] = yi[c];
        }

        // halo row y0+16 (one warp, reuses U0 register arrays)
        if (yl == 0) {
            int yh = (y0 + 16) & 31;
            int sh = (x << 15) | (yh << 10) | (z << 5) | t;
            int sh_px = (sh & ~(31 << 15)) | (((x + 1) & 31) << 15);
            ldU(Ur, Ui, 0, sh, U0r, U0i);
            ldv(xr, xi, 7, sh_px, vr, vi);
            mv(U0r, U0i, vr, vi, 1.f, yr, yi);
#pragma unroll
            for (int c = 0; c < 3; c++) {
                tmp_s[c][16][t] = yr[c];
                tmp_s[3 + c][16][t] = yi[c];
            }
        }
    }

    // Producer side of split barrier: tmp_s rows published; don't wait.
    // Count = 2 * 512 = 1024 arrivals (HW max; each thread arrives then syncs).
    __threadfence_block();
    asm volatile("bar.arrive 1, 1024;" ::: "memory");

    // ---- mu = 2: ch3 ----
    {
        float U2r[9], U2i[9];
        ldU(Ur, Ui, 2, s, U2r, U2i);
        ldv(xr, xi, 3, s_pz, vr, vi);
        mv(U2r, U2i, vr, vi, eta2, yr, yi);
        stv(out, 3, s, yr, yi);
    }

    // ---- mu = 3: ch4 ----
    {
        float U3r[9], U3i[9];
        ldU(Ur, Ui, 3, s, U3r, U3i);
        ldv(xr, xi, 4, s_pt, vr, vi);
        mv(U3r, U3i, vr, vi, eta3, yr, yi);
        stv(out, 4, s, yr, yi);
    }

    // ---- mu = 1 block: U1(s) serves ch2, ch6, ch7 second hop ----
    {
        float U1r[9], U1i[9];
        ldU(Ur, Ui, 1, s, U1r, U1i);

        // ch2: out2(s) = eta1(s) U1(s) x2(s + y_hat)
        ldv(xr, xi, 2, s_py, vr, vi);
        mv(U1r, U1i, vr, vi, eta1, yr, yi);
        stv(out, 2, s, yr, yi);

        // ch6 (scatter): out6(s + y_hat) = eta1(s) U1^dag(s) x6(s)
        ldv(xr, xi, 6, s, vr, vi);
        mvdag(U1r, U1i, vr, vi, eta1, yr, yi);
        stv(out, 6, s_py, yr, yi);

        // Consumer side: wait (usually already released) before reading the
        // neighbor warp's tmp row.
        asm volatile("bar.sync 1, 1024;" ::: "memory");

        // ch7: out7(s) = eta1(s) U1(s) tmp(s + y_hat)   [smem]
#pragma unroll
        for (int c = 0; c < 3; c++) {
            vr[c] = tmp_s[c][yl + 1][t];
            vi[c] = tmp_s[3 + c][yl + 1][t];
        }
        mv(U1r, U1i, vr, vi, eta1, yr, yi);
        stv(out, 7, s, yr, yi);
    }
}

extern "C" void kernel_launch(void* const* d_in, const int* in_sizes, int n_in,
                              void* d_out, int out_size) {
    const float* xr = (const float*)d_in[0];
    const float* xi = (const float*)d_in[1];
    const float* Ur = (const float*)d_in[2];
    const float* Ui = (const float*)d_in[3];
    float* out = (float*)d_out;

    k_fused<<<2048, 512>>>(xr, xi, Ur, Ui, out);
}

// round 17
// speedup vs baseline: 1.0493x; 1.0493x over previous
#include <cuda_runtime.h>

// Staggered parallel transport, 8 paths, 32^4 lattice — fused single kernel.
// R14 structure (256-thread y:8 tile, register U, smem ch7 intermediate) with
// PAIRWISE named barriers: warp yl consumes only row yl+1, so each consumer
// syncs a 2-warp barrier with exactly its producer instead of a block-wide
// barrier coupled to the slowest of 8 warps (incl. the 2x-work halo warp).
//
// Layouts (row-major, metadata order):
//   d_in[0] x_re : (8, V, 3) float    d_in[1] x_im : (8, V, 3)
//   d_in[2] U_re : (4, V, 9) float    d_in[3] U_im : (4, V, 9)
//   d_out        : (2, 8, V, 3) float   (re block then im block)
// site s = ((x*32 + y)*32 + z)*32 + t
//
// Channels:
//   0: copy            1: fwd mu=0       2: fwd mu=1   3: fwd mu=2
//   4: fwd mu=3        5: bwd mu=0 (scatter)   6: bwd mu=1 (scatter)
//   7: fwd mu=0 then fwd mu=1  — first hop in SMEM (y-tiled block + halo)
//
// Barrier plan (count 64 = 2 warps each):
//   rows 1..7 : produced by warp i -> barrier i ; consumed by warp i-1
//   row  8    : produced by warp 0 (halo) -> barrier 8 ; consumed by warp 7
//   warp yl arrives at (yl==0 ? 8 : yl), syncs at (yl+1).

#define VOL (32 * 32 * 32 * 32)

__device__ __forceinline__ void mv(const float* __restrict__ Ur,
                                   const float* __restrict__ Ui,
                                   const float* vr, const float* vi,
                                   float sgn, float* yr, float* yi) {
#pragma unroll
    for (int a = 0; a < 3; a++) {
        float sr = 0.f, si = 0.f;
#pragma unroll
        for (int b = 0; b < 3; b++) {
            float ur = Ur[a * 3 + b], ui = Ui[a * 3 + b];
            sr = fmaf(ur, vr[b], sr);
            sr = fmaf(-ui, vi[b], sr);
            si = fmaf(ur, vi[b], si);
            si = fmaf(ui, vr[b], si);
        }
        yr[a] = sgn * sr;
        yi[a] = sgn * si;
    }
}

__device__ __forceinline__ void mvdag(const float* __restrict__ Ur,
                                      const float* __restrict__ Ui,
                                      const float* vr, const float* vi,
                                      float sgn, float* yr, float* yi) {
#pragma unroll
    for (int a = 0; a < 3; a++) {
        float sr = 0.f, si = 0.f;
#pragma unroll
        for (int b = 0; b < 3; b++) {
            float ur = Ur[b * 3 + a], ui = Ui[b * 3 + a];  // conj-transpose
            sr = fmaf(ur, vr[b], sr);
            sr = fmaf(ui, vi[b], sr);
            si = fmaf(ur, vi[b], si);
            si = fmaf(-ui, vr[b], si);
        }
        yr[a] = sgn * sr;
        yi[a] = sgn * si;
    }
}

__device__ __forceinline__ void ldv(const float* __restrict__ xr,
                                    const float* __restrict__ xi,
                                    int ch, int s, float* vr, float* vi) {
    int b = (ch * VOL + s) * 3;
#pragma unroll
    for (int c = 0; c < 3; c++) {
        vr[c] = __ldg(xr + b + c);
        vi[c] = __ldg(xi + b + c);
    }
}

__device__ __forceinline__ void ldU(const float* __restrict__ Ur,
                                    const float* __restrict__ Ui,
                                    int mu, int s, float* ur, float* ui) {
    int b = (mu * VOL + s) * 9;
#pragma unroll
    for (int k = 0; k < 9; k++) {
        ur[k] = __ldg(Ur + b + k);
        ui[k] = __ldg(Ui + b + k);
    }
}

__device__ __forceinline__ void stv(float* __restrict__ out, int ch, int s,
                                    const float* yr, const float* yi) {
    int br = (ch * VOL + s) * 3;
    int bi = ((8 + ch) * VOL + s) * 3;
#pragma unroll
    for (int c = 0; c < 3; c++) {
        out[br + c] = yr[c];
        out[bi + c] = yi[c];
    }
}

__global__ void __launch_bounds__(256, 4)
k_fused(const float* __restrict__ xr, const float* __restrict__ xi,
        const float* __restrict__ Ur, const float* __restrict__ Ui,
        float* __restrict__ out) {
    // smem tmp for ch7 first hop: [component 0..5][y-row 0..8][t]
    __shared__ float tmp_s[6][9][32];

    int tid = threadIdx.x;
    int t = tid & 31;
    int yl = tid >> 5;            // 0..7

    int bid = blockIdx.x;         // 0..4095
    int y0 = (bid & 3) << 3;      // {0,8,16,24}
    int z = (bid >> 2) & 31;
    int x = bid >> 7;

    int y = y0 + yl;
    int s = (x << 15) | (y << 10) | (z << 5) | t;

    int s_px = (s & ~(31 << 15)) | (((x + 1) & 31) << 15);
    int s_py = (s & ~(31 << 10)) | (((y + 1) & 31) << 10);
    int s_pz = (s & ~(31 << 5)) | (((z + 1) & 31) << 5);
    int s_pt = (s & ~31) | ((t + 1) & 31);

    float eta1 = (x & 1) ? -1.f : 1.f;            // (-1)^x
    float eta2 = ((x ^ y) & 1) ? -1.f : 1.f;      // (-1)^(x+y)
    float eta3 = ((x ^ y ^ z) & 1) ? -1.f : 1.f;  // (-1)^(x+y+z)

    int bar_prod = (yl == 0) ? 8 : yl;   // barrier this warp produces for
    int bar_cons = yl + 1;               // barrier this warp consumes from

    float vr[3], vi[3], yr[3], yi[3];

    // ch0: identity copy (short live range, early MLP)
    ldv(xr, xi, 0, s, vr, vi);
    stv(out, 0, s, vr, vi);

    // ---- mu = 0 block: U0(s) serves ch1, ch5, and the ch7 first hop ----
    {
        float U0r[9], U0i[9];
        ldU(Ur, Ui, 0, s, U0r, U0i);

        // ch1: out1(s) = U0(s) x1(s + x_hat)       (eta0 = 1)
        ldv(xr, xi, 1, s_px, vr, vi);
        mv(U0r, U0i, vr, vi, 1.f, yr, yi);
        stv(out, 1, s, yr, yi);

        // ch5 (scatter): out5(s + x_hat) = U0^dag(s) x5(s)
        ldv(xr, xi, 5, s, vr, vi);
        mvdag(U0r, U0i, vr, vi, 1.f, yr, yi);
        stv(out, 5, s_px, yr, yi);

        // ch7 first hop -> smem: tmp(s) = U0(s) x7(s + x_hat)
        ldv(xr, xi, 7, s_px, vr, vi);
        mv(U0r, U0i, vr, vi, 1.f, yr, yi);
#pragma unroll
        for (int c = 0; c < 3; c++) {
            tmp_s[c][yl][t] = yr[c];
            tmp_s[3 + c][yl][t] = yi[c];
        }

        // halo row y0+8 (warp 0 only, reuses U0 register arrays)
        if (yl == 0) {
            int yh = (y0 + 8) & 31;
            int sh = (x << 15) | (yh << 10) | (z << 5) | t;
            int sh_px = (sh & ~(31 << 15)) | (((x + 1) & 31) << 15);
            ldU(Ur, Ui, 0, sh, U0r, U0i);
            ldv(xr, xi, 7, sh_px, vr, vi);
            mv(U0r, U0i, vr, vi, 1.f, yr, yi);
#pragma unroll
            for (int c = 0; c < 3; c++) {
                tmp_s[c][8][t] = yr[c];
                tmp_s[3 + c][8][t] = yi[c];
            }
        }
    }

    // Producer arrive: publish this warp's tmp row to its one consumer.
    __threadfence_block();
    asm volatile("bar.arrive %0, 64;" :: "r"(bar_prod) : "memory");

    // ---- mu = 2: ch3 ----
    {
        float U2r[9], U2i[9];
        ldU(Ur, Ui, 2, s, U2r, U2i);
        ldv(xr, xi, 3, s_pz, vr, vi);
        mv(U2r, U2i, vr, vi, eta2, yr, yi);
        stv(out, 3, s, yr, yi);
    }

    // ---- mu = 3: ch4 ----
    {
        float U3r[9], U3i[9];
        ldU(Ur, Ui, 3, s, U3r, U3i);
        ldv(xr, xi, 4, s_pt, vr, vi);
        mv(U3r, U3i, vr, vi, eta3, yr, yi);
        stv(out, 4, s, yr, yi);
    }

    // ---- mu = 1 block: U1(s) serves ch2, ch6, ch7 second hop ----
    {
        float U1r[9], U1i[9];
        ldU(Ur, Ui, 1, s, U1r, U1i);

        // ch2: out2(s) = eta1(s) U1(s) x2(s + y_hat)
        ldv(xr, xi, 2, s_py, vr, vi);
        mv(U1r, U1i, vr, vi, eta1, yr, yi);
        stv(out, 2, s, yr, yi);

        // ch6 (scatter): out6(s + y_hat) = eta1(s) U1^dag(s) x6(s)
        ldv(xr, xi, 6, s, vr, vi);
        mvdag(U1r, U1i, vr, vi, eta1, yr, yi);
        stv(out, 6, s_py, yr, yi);

        // Consumer sync: wait only for THIS warp's producer (2-warp barrier).
        asm volatile("bar.sync %0, 64;" :: "r"(bar_cons) : "memory");

        // ch7: out7(s) = eta1(s) U1(s) tmp(s + y_hat)   [smem]
#pragma unroll
        for (int c = 0; c < 3; c++) {
            vr[c] = tmp_s[c][yl + 1][t];
            vi[c] = tmp_s[3 + c][yl + 1][t];
        }
        mv(U1r, U1i, vr, vi, eta1, yr, yi);
        stv(out, 7, s, yr, yi);
    }
}

extern "C" void kernel_launch(void* const* d_in, const int* in_sizes, int n_in,
                              void* d_out, int out_size) {
    const float* xr = (const float*)d_in[0];
    const float* xi = (const float*)d_in[1];
    const float* Ur = (const float*)d_in[2];
    const float* Ui = (const float*)d_in[3];
    float* out = (float*)d_out;

    k_fused<<<4096, 256>>>(xr, xi, Ur, Ui, out);
}